// round 1
// baseline (speedup 1.0000x reference)
#include <cuda_runtime.h>

#define NN 50000
#define EE 800000

// ---------------- scratch (device globals; no allocation) ----------------
__device__ float g_h[NN * 128];     // layer input/output node features
__device__ float g_feat[NN * 128];  // fc output of current layer
__device__ float g_el[NN * 4];
__device__ float g_er[NN * 4];
__device__ float g_m[NN * 4];
__device__ float g_s[NN * 4];
__device__ float g_rst[NN * 128];
__device__ float g_ex[EE * 4];

// ---------------- helpers ----------------
__device__ __forceinline__ void atomicMaxFloat(float* addr, float val) {
    // sign-split trick: positives via int max, negatives via uint min.
    if (val >= 0.0f)
        atomicMax((int*)addr, __float_as_int(val));
    else
        atomicMin((unsigned int*)addr, __float_as_uint(val));
}

__device__ __forceinline__ float leaky(float x) {
    return x >= 0.0f ? x : 0.2f * x;
}

// ---------------- init: m=-1e30, s=0, rst=0 ----------------
template <int H, int D>
__global__ void init_buf() {
    int i = blockIdx.x * blockDim.x + threadIdx.x;
    if (i < NN * H * D) g_rst[i] = 0.0f;
    if (i < NN * H) { g_m[i] = -1e30f; g_s[i] = 0.0f; }
}

// ---------------- GEMM: feat[N,128] = A[N,K] @ W[K,128] ----------------
template <int K, bool FROM_GH>
__global__ void gemm128(const float* __restrict__ A, const float* __restrict__ W) {
    __shared__ float sW[64][128];
    __shared__ float sA[32][64];
    const int j = threadIdx.x;          // 0..127 output column
    const int row0 = blockIdx.x * 32;

    float acc[32];
#pragma unroll
    for (int r = 0; r < 32; r++) acc[r] = 0.0f;

    for (int kc = 0; kc < K; kc += 64) {
        // load W chunk [64,128]
        for (int i = threadIdx.x; i < 64 * 128; i += 128) {
            sW[i >> 7][i & 127] = W[(kc + (i >> 7)) * 128 + (i & 127)];
        }
        // load A chunk [32,64]
        for (int i = threadIdx.x; i < 32 * 64; i += 128) {
            int r = i >> 6, k = i & 63;
            int row = row0 + r;
            float v = 0.0f;
            if (row < NN) {
                if (FROM_GH) v = g_h[row * K + kc + k];
                else         v = A[row * K + kc + k];
            }
            sA[r][k] = v;
        }
        __syncthreads();
#pragma unroll 4
        for (int kk = 0; kk < 64; kk++) {
            float w = sW[kk][j];
#pragma unroll
            for (int r = 0; r < 32; r++) acc[r] += sA[r][kk] * w;
        }
        __syncthreads();
    }
#pragma unroll
    for (int r = 0; r < 32; r++) {
        int row = row0 + r;
        if (row < NN) g_feat[row * 128 + j] = acc[r];
    }
}

// ---------------- layer2 GEMM: feat[N,4] = g_h[N,128] @ W[128,4] ----------------
__global__ void gemm_small(const float* __restrict__ W) {
    int n = blockIdx.x * blockDim.x + threadIdx.x;
    if (n >= NN) return;
    float a0 = 0, a1 = 0, a2 = 0, a3 = 0;
    const float* hr = &g_h[n * 128];
#pragma unroll 8
    for (int k = 0; k < 128; k++) {
        float hv = hr[k];
        float4 w = *(const float4*)&W[k * 4];
        a0 += hv * w.x; a1 += hv * w.y; a2 += hv * w.z; a3 += hv * w.w;
    }
    *(float4*)&g_feat[n * 4] = make_float4(a0, a1, a2, a3);
}

// ---------------- per-(node,head) attention scores el/er ----------------
template <int H, int D>
__global__ void scores(const float* __restrict__ al, const float* __restrict__ ar) {
    int wid = (blockIdx.x * blockDim.x + threadIdx.x) >> 5;
    int lane = threadIdx.x & 31;
    if (wid >= NN * H) return;
    int n = wid / H, h = wid - n * H;
    float v = 0.0f, u = 0.0f;
    if (lane < D) {
        float f = g_feat[n * (H * D) + h * D + lane];
        v = f * al[h * D + lane];
        u = f * ar[h * D + lane];
    }
#pragma unroll
    for (int o = 16; o; o >>= 1) {
        v += __shfl_xor_sync(0xFFFFFFFFu, v, o);
        u += __shfl_xor_sync(0xFFFFFFFFu, u, o);
    }
    if (lane == 0) { g_el[n * H + h] = v; g_er[n * H + h] = u; }
}

// ---------------- edge segment-max ----------------
template <int H>
__global__ void edge_max(const int* __restrict__ src, const int* __restrict__ dst) {
    int e = blockIdx.x * blockDim.x + threadIdx.x;
    if (e >= EE) return;
    int s = src[e], d = dst[e];
#pragma unroll
    for (int h = 0; h < H; h++) {
        float x = leaky(g_el[s * H + h] + g_er[d * H + h]);
        atomicMaxFloat(&g_m[d * H + h], x);
    }
}

// ---------------- edge exp + segment-sum (stores ex) ----------------
template <int H>
__global__ void edge_expsum(const int* __restrict__ src, const int* __restrict__ dst) {
    int e = blockIdx.x * blockDim.x + threadIdx.x;
    if (e >= EE) return;
    int s = src[e], d = dst[e];
#pragma unroll
    for (int h = 0; h < H; h++) {
        float x = leaky(g_el[s * H + h] + g_er[d * H + h]);
        float m = g_m[d * H + h];
        m = (m > -1e29f) ? m : 0.0f;  // zero-in-degree safety
        float ex = __expf(x - m);
        g_ex[e * H + h] = ex;
        atomicAdd(&g_s[d * H + h], ex);
    }
}

// ---------------- edge aggregation, H=4 D=32: warp per edge ----------------
__global__ void edge_agg128(const int* __restrict__ src, const int* __restrict__ dst) {
    int w = (blockIdx.x * blockDim.x + threadIdx.x) >> 5;
    int lane = threadIdx.x & 31;
    if (w >= EE) return;
    int s = src[w], d = dst[w];
    float4 exv = *(const float4*)&g_ex[w * 4];
    float4 sv  = *(const float4*)&g_s[d * 4];
    float a0 = exv.x / sv.x;
    float a1 = exv.y / sv.y;
    float a2 = exv.z / sv.z;
    float a3 = exv.w / sv.w;
    const float* fs = &g_feat[s * 128];
    float* rd = &g_rst[d * 128];
    atomicAdd(&rd[lane],      fs[lane]      * a0);
    atomicAdd(&rd[32 + lane], fs[32 + lane] * a1);
    atomicAdd(&rd[64 + lane], fs[64 + lane] * a2);
    atomicAdd(&rd[96 + lane], fs[96 + lane] * a3);
}

// ---------------- edge aggregation, H=1 D=4: thread per edge ----------------
__global__ void edge_agg4(const int* __restrict__ src, const int* __restrict__ dst) {
    int e = blockIdx.x * blockDim.x + threadIdx.x;
    if (e >= EE) return;
    int s = src[e], d = dst[e];
    float a = g_ex[e] / g_s[d];
    float4 f = *(const float4*)&g_feat[s * 4];
    atomicAdd(&g_rst[d * 4 + 0], f.x * a);
    atomicAdd(&g_rst[d * 4 + 1], f.y * a);
    atomicAdd(&g_rst[d * 4 + 2], f.z * a);
    atomicAdd(&g_rst[d * 4 + 3], f.w * a);
}

// ---------------- epilogue: bias + residual + ELU ----------------
__global__ void epilogue(const float* __restrict__ b, int C, int residual, int act,
                         float* __restrict__ out) {
    int i = blockIdx.x * blockDim.x + threadIdx.x;
    if (i >= NN * C) return;
    int j = i % C;
    float v = g_rst[i] + b[j];
    if (residual) v += g_h[i];
    if (act) v = (v > 0.0f) ? v : (__expf(v) - 1.0f);
    if (out) out[i] = v;
    else     g_h[i] = v;
}

// ---------------- launch ----------------
extern "C" void kernel_launch(void* const* d_in, const int* in_sizes, int n_in,
                              void* d_out, int out_size) {
    const float* x   = (const float*)d_in[0];
    const int*   src = (const int*)d_in[1];
    const int*   dst = (const int*)d_in[2];
    const float* W0  = (const float*)d_in[3];
    const float* al0 = (const float*)d_in[4];
    const float* ar0 = (const float*)d_in[5];
    const float* b0  = (const float*)d_in[6];
    const float* W1  = (const float*)d_in[7];
    const float* al1 = (const float*)d_in[8];
    const float* ar1 = (const float*)d_in[9];
    const float* b1  = (const float*)d_in[10];
    const float* W2  = (const float*)d_in[11];
    const float* al2 = (const float*)d_in[12];
    const float* ar2 = (const float*)d_in[13];
    const float* b2  = (const float*)d_in[14];
    float* out = (float*)d_out;

    const int TB = 256;
    const int gN128  = (NN * 128 + TB - 1) / TB;
    const int gN4x32 = (NN * 4 * 32 + TB - 1) / TB;   // N*H warps, H=4
    const int gN1x32 = (NN * 1 * 32 + TB - 1) / TB;   // N*H warps, H=1
    const int gE     = (EE + TB - 1) / TB;
    const int gE32   = (EE * 32 + TB - 1) / TB;       // warp per edge
    const int gGemm  = (NN + 31) / 32;
    const int gN     = (NN + TB - 1) / TB;
    const int gN4    = (NN * 4 + TB - 1) / TB;

    // ---------------- layer 0: 64 -> 4x32, act, no residual ----------------
    init_buf<4, 32><<<gN128, TB>>>();
    gemm128<64, false><<<gGemm, 128>>>(x, W0);
    scores<4, 32><<<gN4x32, TB>>>(al0, ar0);
    edge_max<4><<<gE, TB>>>(src, dst);
    edge_expsum<4><<<gE, TB>>>(src, dst);
    edge_agg128<<<gE32, TB>>>(src, dst);
    epilogue<<<gN128, TB>>>(b0, 128, 0, 1, nullptr);

    // ---------------- layer 1: 128 -> 4x32, act, identity residual ----------------
    init_buf<4, 32><<<gN128, TB>>>();
    gemm128<128, true><<<gGemm, 128>>>(nullptr, W1);
    scores<4, 32><<<gN4x32, TB>>>(al1, ar1);
    edge_max<4><<<gE, TB>>>(src, dst);
    edge_expsum<4><<<gE, TB>>>(src, dst);
    edge_agg128<<<gE32, TB>>>(src, dst);
    epilogue<<<gN128, TB>>>(b1, 128, 1, 1, nullptr);

    // ---------------- layer 2: 128 -> 1x4, no act, no residual ----------------
    init_buf<1, 4><<<gN128, TB>>>();
    gemm_small<<<gN, TB>>>(W2);
    scores<1, 4><<<gN1x32, TB>>>(al2, ar2);
    edge_max<1><<<gE, TB>>>(src, dst);
    edge_expsum<1><<<gE, TB>>>(src, dst);
    edge_agg4<<<gE, TB>>>(src, dst);
    epilogue<<<gN4, TB>>>(b2, 4, 0, 0, out);
}

// round 2
// speedup vs baseline: 2.3471x; 2.3471x over previous
#include <cuda_runtime.h>

#define NN 50000
#define EE 800000

// ---------------- scratch (device globals; no allocation) ----------------
__device__ __align__(16) float g_h[NN * 128];
__device__ __align__(16) float g_feat[NN * 128];
__device__ __align__(16) float g_el[NN * 4];
__device__ __align__(16) float g_er[NN * 4];
__device__ int g_deg[NN];
__device__ int g_off[NN + 1];
__device__ int g_cur[NN];
__device__ int g_esrc[EE];

__device__ __forceinline__ float leaky(float x) {
    return x >= 0.0f ? x : 0.2f * x;
}

// ================= CSR build =================
__global__ void k_zero() {
    int i = blockIdx.x * blockDim.x + threadIdx.x;
    if (i < NN) g_deg[i] = 0;
}

__global__ void k_hist(const int* __restrict__ dst) {
    int e = blockIdx.x * blockDim.x + threadIdx.x;
    if (e < EE) atomicAdd(&g_deg[dst[e]], 1);
}

// single-block exclusive scan of g_deg -> g_off (and g_cur)
__global__ void k_scan() {
    __shared__ int sp[1024];
    int tid = threadIdx.x;
    const int chunk = (NN + 1023) >> 10;  // 49
    int beg = tid * chunk;
    int end = min(beg + chunk, NN);
    int s = 0;
    for (int i = beg; i < end; i++) s += g_deg[i];
    sp[tid] = s;
    __syncthreads();
    // Kogge-Stone inclusive scan over partials
    for (int off = 1; off < 1024; off <<= 1) {
        int v = (tid >= off) ? sp[tid - off] : 0;
        __syncthreads();
        sp[tid] += v;
        __syncthreads();
    }
    int run = (tid == 0) ? 0 : sp[tid - 1];
    for (int i = beg; i < end; i++) {
        g_off[i] = run;
        g_cur[i] = run;
        run += g_deg[i];
    }
    if (tid == 1023) g_off[NN] = sp[1023];
}

__global__ void k_scatter(const int* __restrict__ src, const int* __restrict__ dst) {
    int e = blockIdx.x * blockDim.x + threadIdx.x;
    if (e < EE) {
        int p = atomicAdd(&g_cur[dst[e]], 1);
        g_esrc[p] = src[e];
    }
}

// ================= GEMM: feat[N,128] = A[N,K] @ W[K,128] =================
// BM=64, BN=128, BK=16, 256 threads, 8x4 register tile per thread.
template <int K, bool FROM_GH>
__global__ void gemm128(const float* __restrict__ A, const float* __restrict__ W) {
    __shared__ float sA[16][65];   // A^T chunk (padded)
    __shared__ float sB[16][128];
    const int tid = threadIdx.x;
    const int tx = tid & 31;       // col group -> cols tx*4..+3
    const int ty = tid >> 5;       // row group -> rows ty*8..+7
    const int row0 = blockIdx.x * 64;
    const float* Ap = FROM_GH ? g_h : A;

    float acc[8][4];
#pragma unroll
    for (int i = 0; i < 8; i++)
#pragma unroll
        for (int j = 0; j < 4; j++) acc[i][j] = 0.0f;

    for (int kc = 0; kc < K; kc += 16) {
        // load A tile [64,16] transposed into sA
        {
            int m = tid >> 2;             // 0..63
            int k = (tid & 3) * 4;        // 0,4,8,12
            int row = row0 + m;
            float4 v = make_float4(0.f, 0.f, 0.f, 0.f);
            if (row < NN) v = *(const float4*)&Ap[row * K + kc + k];
            sA[k + 0][m] = v.x;
            sA[k + 1][m] = v.y;
            sA[k + 2][m] = v.z;
            sA[k + 3][m] = v.w;
        }
        // load B tile [16,128]
#pragma unroll
        for (int i = tid; i < 16 * 32; i += 256) {
            int r = i >> 5, c = (i & 31) * 4;
            *(float4*)&sB[r][c] = *(const float4*)&W[(kc + r) * 128 + c];
        }
        __syncthreads();
#pragma unroll
        for (int kk = 0; kk < 16; kk++) {
            float b[4];
            *(float4*)b = *(float4*)&sB[kk][tx * 4];
            float a[8];
#pragma unroll
            for (int i = 0; i < 8; i++) a[i] = sA[kk][ty * 8 + i];
#pragma unroll
            for (int i = 0; i < 8; i++)
#pragma unroll
                for (int j = 0; j < 4; j++) acc[i][j] += a[i] * b[j];
        }
        __syncthreads();
    }
#pragma unroll
    for (int i = 0; i < 8; i++) {
        int row = row0 + ty * 8 + i;
        if (row < NN)
            *(float4*)&g_feat[row * 128 + tx * 4] =
                make_float4(acc[i][0], acc[i][1], acc[i][2], acc[i][3]);
    }
}

// ---------------- layer2 GEMM: feat[N,4] = g_h[N,128] @ W[128,4] ----------------
__global__ void gemm_small(const float* __restrict__ W) {
    int n = blockIdx.x * blockDim.x + threadIdx.x;
    if (n >= NN) return;
    float a0 = 0, a1 = 0, a2 = 0, a3 = 0;
    const float* hr = &g_h[n * 128];
#pragma unroll 8
    for (int k = 0; k < 128; k++) {
        float hv = hr[k];
        float4 w = *(const float4*)&W[k * 4];
        a0 += hv * w.x; a1 += hv * w.y; a2 += hv * w.z; a3 += hv * w.w;
    }
    *(float4*)&g_feat[n * 4] = make_float4(a0, a1, a2, a3);
}

// ---------------- per-(node,head) attention halves el/er ----------------
template <int H, int D>
__global__ void scores(const float* __restrict__ al, const float* __restrict__ ar) {
    int wid = (blockIdx.x * blockDim.x + threadIdx.x) >> 5;
    int lane = threadIdx.x & 31;
    if (wid >= NN * H) return;
    int n = wid / H, h = wid - n * H;
    float v = 0.0f, u = 0.0f;
    if (lane < D) {
        float f = g_feat[n * (H * D) + h * D + lane];
        v = f * al[h * D + lane];
        u = f * ar[h * D + lane];
    }
#pragma unroll
    for (int o = 16; o; o >>= 1) {
        v += __shfl_xor_sync(0xFFFFFFFFu, v, o);
        u += __shfl_xor_sync(0xFFFFFFFFu, u, o);
    }
    if (lane == 0) { g_el[n * H + h] = v; g_er[n * H + h] = u; }
}

// ================= fused per-node GAT (H=4, D=32): max + softmax-sum +
// aggregate + bias/residual/ELU, warp per dst node, no atomics =================
__global__ void node_gat128(const float* __restrict__ bias, int residual, int act) {
    __shared__ float4 sh[8][64];   // staged exp values per warp
    const int wl = threadIdx.x >> 5;
    const int lane = threadIdx.x & 31;
    const int node = (blockIdx.x * blockDim.x + threadIdx.x) >> 5;
    if (node >= NN) return;
    const int beg = g_off[node], end = g_off[node + 1];
    const float4 erd = *(const float4*)&g_er[node * 4];

    // pass A: segment max, lane-strided
    float m0 = -1e30f, m1 = -1e30f, m2 = -1e30f, m3 = -1e30f;
    for (int i = beg + lane; i < end; i += 32) {
        int s = g_esrc[i];
        float4 el = *(const float4*)&g_el[s * 4];
        m0 = fmaxf(m0, leaky(el.x + erd.x));
        m1 = fmaxf(m1, leaky(el.y + erd.y));
        m2 = fmaxf(m2, leaky(el.z + erd.z));
        m3 = fmaxf(m3, leaky(el.w + erd.w));
    }
#pragma unroll
    for (int o = 16; o; o >>= 1) {
        m0 = fmaxf(m0, __shfl_xor_sync(0xFFFFFFFFu, m0, o));
        m1 = fmaxf(m1, __shfl_xor_sync(0xFFFFFFFFu, m1, o));
        m2 = fmaxf(m2, __shfl_xor_sync(0xFFFFFFFFu, m2, o));
        m3 = fmaxf(m3, __shfl_xor_sync(0xFFFFFFFFu, m3, o));
    }

    // pass B: exp-sum + weighted feature aggregation (chunks of 64 edges)
    float s0 = 0, s1 = 0, s2 = 0, s3 = 0;
    float a0 = 0, a1 = 0, a2 = 0, a3 = 0;
    for (int c = beg; c < end; c += 64) {
        int cnt = min(64, end - c);
        for (int t = lane; t < cnt; t += 32) {
            int s = g_esrc[c + t];
            float4 el = *(const float4*)&g_el[s * 4];
            float e0 = __expf(leaky(el.x + erd.x) - m0);
            float e1 = __expf(leaky(el.y + erd.y) - m1);
            float e2 = __expf(leaky(el.z + erd.z) - m2);
            float e3 = __expf(leaky(el.w + erd.w) - m3);
            sh[wl][t] = make_float4(e0, e1, e2, e3);
            s0 += e0; s1 += e1; s2 += e2; s3 += e3;
        }
        __syncwarp();
#pragma unroll 2
        for (int i = 0; i < cnt; i++) {
            int s = g_esrc[c + i];            // broadcast
            float4 ev = sh[wl][i];
            const float* f = &g_feat[s * 128];
            a0 += ev.x * f[lane];
            a1 += ev.y * f[32 + lane];
            a2 += ev.z * f[64 + lane];
            a3 += ev.w * f[96 + lane];
        }
        __syncwarp();
    }
#pragma unroll
    for (int o = 16; o; o >>= 1) {
        s0 += __shfl_xor_sync(0xFFFFFFFFu, s0, o);
        s1 += __shfl_xor_sync(0xFFFFFFFFu, s1, o);
        s2 += __shfl_xor_sync(0xFFFFFFFFu, s2, o);
        s3 += __shfl_xor_sync(0xFFFFFFFFu, s3, o);
    }
    float i0 = (end > beg) ? 1.0f / s0 : 0.0f;
    float i1 = (end > beg) ? 1.0f / s1 : 0.0f;
    float i2 = (end > beg) ? 1.0f / s2 : 0.0f;
    float i3 = (end > beg) ? 1.0f / s3 : 0.0f;

    float v0 = a0 * i0 + bias[lane];
    float v1 = a1 * i1 + bias[32 + lane];
    float v2 = a2 * i2 + bias[64 + lane];
    float v3 = a3 * i3 + bias[96 + lane];
    int base = node * 128;
    if (residual) {
        v0 += g_h[base + lane];
        v1 += g_h[base + 32 + lane];
        v2 += g_h[base + 64 + lane];
        v3 += g_h[base + 96 + lane];
    }
    if (act) {
        v0 = v0 > 0.f ? v0 : __expf(v0) - 1.f;
        v1 = v1 > 0.f ? v1 : __expf(v1) - 1.f;
        v2 = v2 > 0.f ? v2 : __expf(v2) - 1.f;
        v3 = v3 > 0.f ? v3 : __expf(v3) - 1.f;
    }
    g_h[base + lane] = v0;
    g_h[base + 32 + lane] = v1;
    g_h[base + 64 + lane] = v2;
    g_h[base + 96 + lane] = v3;
}

// ================= fused per-node GAT (H=1, D=4): layer 2, writes out ========
__global__ void node_gat4(const float* __restrict__ bias, float* __restrict__ out) {
    const int lane = threadIdx.x & 31;
    const int node = (blockIdx.x * blockDim.x + threadIdx.x) >> 5;
    if (node >= NN) return;
    const int beg = g_off[node], end = g_off[node + 1];
    const float erd = g_er[node];

    float m = -1e30f;
    for (int i = beg + lane; i < end; i += 32) {
        int s = g_esrc[i];
        m = fmaxf(m, leaky(g_el[s] + erd));
    }
#pragma unroll
    for (int o = 16; o; o >>= 1) m = fmaxf(m, __shfl_xor_sync(0xFFFFFFFFu, m, o));

    float ssum = 0.f;
    float ax = 0.f, ay = 0.f, az = 0.f, aw = 0.f;
    for (int i = beg + lane; i < end; i += 32) {
        int s = g_esrc[i];
        float e = __expf(leaky(g_el[s] + erd) - m);
        ssum += e;
        float4 f = *(const float4*)&g_feat[s * 4];
        ax += e * f.x; ay += e * f.y; az += e * f.z; aw += e * f.w;
    }
#pragma unroll
    for (int o = 16; o; o >>= 1) {
        ssum += __shfl_xor_sync(0xFFFFFFFFu, ssum, o);
        ax += __shfl_xor_sync(0xFFFFFFFFu, ax, o);
        ay += __shfl_xor_sync(0xFFFFFFFFu, ay, o);
        az += __shfl_xor_sync(0xFFFFFFFFu, az, o);
        aw += __shfl_xor_sync(0xFFFFFFFFu, aw, o);
    }
    if (lane == 0) {
        float inv = (end > beg) ? 1.0f / ssum : 0.0f;
        float4 o4 = make_float4(ax * inv + bias[0], ay * inv + bias[1],
                                az * inv + bias[2], aw * inv + bias[3]);
        *(float4*)&out[node * 4] = o4;
    }
}

// ---------------- launch ----------------
extern "C" void kernel_launch(void* const* d_in, const int* in_sizes, int n_in,
                              void* d_out, int out_size) {
    const float* x   = (const float*)d_in[0];
    const int*   src = (const int*)d_in[1];
    const int*   dst = (const int*)d_in[2];
    const float* W0  = (const float*)d_in[3];
    const float* al0 = (const float*)d_in[4];
    const float* ar0 = (const float*)d_in[5];
    const float* b0  = (const float*)d_in[6];
    const float* W1  = (const float*)d_in[7];
    const float* al1 = (const float*)d_in[8];
    const float* ar1 = (const float*)d_in[9];
    const float* b1  = (const float*)d_in[10];
    const float* W2  = (const float*)d_in[11];
    const float* al2 = (const float*)d_in[12];
    const float* ar2 = (const float*)d_in[13];
    const float* b2  = (const float*)d_in[14];
    float* out = (float*)d_out;

    const int TB = 256;
    const int gN     = (NN + TB - 1) / TB;
    const int gE     = (EE + TB - 1) / TB;
    const int gNw    = (NN * 32 + TB - 1) / TB;         // warp per node
    const int gN4x32 = (NN * 4 * 32 + TB - 1) / TB;     // warp per (node,head)
    const int gN1x32 = (NN * 1 * 32 + TB - 1) / TB;
    const int gGemm  = (NN + 63) / 64;

    // CSR by destination (shared across layers)
    k_zero<<<gN, TB>>>();
    k_hist<<<gE, TB>>>(dst);
    k_scan<<<1, 1024>>>();
    k_scatter<<<gE, TB>>>(src, dst);

    // layer 0: 64 -> 4x32, act, no residual
    gemm128<64, false><<<gGemm, 256>>>(x, W0);
    scores<4, 32><<<gN4x32, TB>>>(al0, ar0);
    node_gat128<<<gNw, TB>>>(b0, 0, 1);

    // layer 1: 128 -> 4x32, act, identity residual
    gemm128<128, true><<<gGemm, 256>>>(nullptr, W1);
    scores<4, 32><<<gN4x32, TB>>>(al1, ar1);
    node_gat128<<<gNw, TB>>>(b1, 1, 1);

    // layer 2: 128 -> 1x4, no act, no residual
    gemm_small<<<gN, TB>>>(W2);
    scores<1, 4><<<gN1x32, TB>>>(al2, ar2);
    node_gat4<<<gNw, TB>>>(b2, out);
}

// round 3
// speedup vs baseline: 2.6560x; 1.1316x over previous
#include <cuda_runtime.h>
#include <cuda_fp16.h>

#define NN 50000
#define EE 800000

// ---------------- scratch (device globals; no allocation) ----------------
__device__ __align__(16) float g_h[NN * 128];      // layer io node features (fp32)
__device__ __align__(16) __half g_feath[NN * 128]; // fc output, head-interleaved half
__device__ __align__(16) float g_feat4[NN * 4];    // layer2 fc output
__device__ __align__(16) float g_el[NN * 4];
__device__ __align__(16) float g_er[NN * 4];
__device__ int g_deg[NN];
__device__ int g_off[NN + 1];
__device__ int g_cur[NN];
__device__ int g_esrc[EE];

__device__ __forceinline__ float leaky(float x) {
    return x >= 0.0f ? x : 0.2f * x;
}

// ================= CSR build =================
__global__ void k_zero() {
    int i = blockIdx.x * blockDim.x + threadIdx.x;
    if (i < NN) g_deg[i] = 0;
}

__global__ void k_hist(const int* __restrict__ dst) {
    int e = blockIdx.x * blockDim.x + threadIdx.x;
    if (e < EE) atomicAdd(&g_deg[dst[e]], 1);
}

__global__ void k_scan() {
    __shared__ int sp[1024];
    int tid = threadIdx.x;
    const int chunk = (NN + 1023) >> 10;
    int beg = tid * chunk;
    int end = min(beg + chunk, NN);
    int s = 0;
    for (int i = beg; i < end; i++) s += g_deg[i];
    sp[tid] = s;
    __syncthreads();
    for (int off = 1; off < 1024; off <<= 1) {
        int v = (tid >= off) ? sp[tid - off] : 0;
        __syncthreads();
        sp[tid] += v;
        __syncthreads();
    }
    int run = (tid == 0) ? 0 : sp[tid - 1];
    for (int i = beg; i < end; i++) {
        g_off[i] = run;
        g_cur[i] = run;
        run += g_deg[i];
    }
    if (tid == 1023) g_off[NN] = sp[1023];
}

__global__ void k_scatter(const int* __restrict__ src, const int* __restrict__ dst) {
    int e = blockIdx.x * blockDim.x + threadIdx.x;
    if (e < EE) {
        int p = atomicAdd(&g_cur[dst[e]], 1);
        g_esrc[p] = src[e];
    }
}

// ================= fused GEMM + scores: feat_h[N,128] (interleaved half),
// el/er[N,4] directly.  BM=64, BN=128, BK=16, 256 threads, 8x4 reg tile. =====
template <int K, bool FROM_GH>
__global__ void gemm_fused(const float* __restrict__ A, const float* __restrict__ W,
                           const float* __restrict__ al, const float* __restrict__ ar) {
    __shared__ __align__(16) unsigned char smem_u[33280];
    float (*sA)[65]    = (float(*)[65])smem_u;               // [16][65]   phase 1
    float (*sB)[128]   = (float(*)[128])(smem_u + 4160);     // [16][128]  phase 1
    __half (*sH)[128]  = (__half(*)[128])smem_u;             // [64][128]  phase 2
    float2 (*sRed)[33] = (float2(*)[33])(smem_u + 16384);    // [64][33]   phase 2

    const int tid = threadIdx.x;
    const int tx = tid & 31;       // cols tx*4..+3
    const int ty = tid >> 5;       // rows ty*8..+7
    const int row0 = blockIdx.x * 64;
    const float* Ap = FROM_GH ? g_h : A;

    float acc[8][4];
#pragma unroll
    for (int i = 0; i < 8; i++)
#pragma unroll
        for (int j = 0; j < 4; j++) acc[i][j] = 0.0f;

    for (int kc = 0; kc < K; kc += 16) {
        {
            int m = tid >> 2;
            int k = (tid & 3) * 4;
            int row = row0 + m;
            float4 v = make_float4(0.f, 0.f, 0.f, 0.f);
            if (row < NN) v = *(const float4*)&Ap[row * K + kc + k];
            sA[k + 0][m] = v.x;
            sA[k + 1][m] = v.y;
            sA[k + 2][m] = v.z;
            sA[k + 3][m] = v.w;
        }
#pragma unroll
        for (int i = tid; i < 16 * 32; i += 256) {
            int r = i >> 5, c = (i & 31) * 4;
            *(float4*)&sB[r][c] = *(const float4*)&W[(kc + r) * 128 + c];
        }
        __syncthreads();
#pragma unroll
        for (int kk = 0; kk < 16; kk++) {
            float b[4];
            *(float4*)b = *(float4*)&sB[kk][tx * 4];
            float a[8];
#pragma unroll
            for (int i = 0; i < 8; i++) a[i] = sA[kk][ty * 8 + i];
#pragma unroll
            for (int i = 0; i < 8; i++)
#pragma unroll
                for (int j = 0; j < 4; j++) acc[i][j] += a[i] * b[j];
        }
        __syncthreads();
    }
    __syncthreads();  // retire sA/sB before phase-2 reuse

    // ---- epilogue: stage interleaved half feat + per-thread score partials ----
    const int h = tx >> 3;          // head 0..3
    const int dbase = (tx & 7) * 4; // dim base within head
    const int P = h >> 1, hb = h & 1;
    float alv[4], arv[4];
#pragma unroll
    for (int j = 0; j < 4; j++) {
        alv[j] = al[h * 32 + dbase + j];
        arv[j] = ar[h * 32 + dbase + j];
    }
#pragma unroll
    for (int i = 0; i < 8; i++) {
        int row = ty * 8 + i;
        float el = 0.f, er = 0.f;
#pragma unroll
        for (int j = 0; j < 4; j++) {
            el += acc[i][j] * alv[j];
            er += acc[i][j] * arv[j];
            sH[row][P * 64 + 2 * (dbase + j) + hb] = __float2half(acc[i][j]);
        }
        sRed[row][tx] = make_float2(el, er);
    }
    __syncthreads();

    // ---- coalesced half-feat writeout (64 rows x 16 float4 each) ----
    {
        const float4* s4 = (const float4*)sH;
        float4* d4 = (float4*)g_feath;
#pragma unroll
        for (int q = 0; q < 4; q++) {
            int idx = q * 256 + tid;        // 0..1023
            int row = idx >> 4;
            if (row0 + row < NN) d4[row0 * 16 + idx] = s4[idx];
        }
    }
    // ---- score reduction: thread -> (row, head) ----
    {
        int row = tid >> 2, hh = tid & 3;
        int node = row0 + row;
        if (node < NN) {
            float el = 0.f, er = 0.f;
#pragma unroll
            for (int k = 0; k < 8; k++) {
                float2 v = sRed[row][hh * 8 + k];
                el += v.x;
                er += v.y;
            }
            g_el[node * 4 + hh] = el;
            g_er[node * 4 + hh] = er;
        }
    }
}

// ---------------- layer2: feat4 = g_h @ W2, el/er fused ----------------
__global__ void gemm_small(const float* __restrict__ W,
                           const float* __restrict__ al2, const float* __restrict__ ar2) {
    int n = blockIdx.x * blockDim.x + threadIdx.x;
    if (n >= NN) return;
    float a0 = 0, a1 = 0, a2 = 0, a3 = 0;
    const float* hr = &g_h[n * 128];
#pragma unroll 8
    for (int k = 0; k < 128; k++) {
        float hv = hr[k];
        float4 w = *(const float4*)&W[k * 4];
        a0 += hv * w.x; a1 += hv * w.y; a2 += hv * w.z; a3 += hv * w.w;
    }
    *(float4*)&g_feat4[n * 4] = make_float4(a0, a1, a2, a3);
    g_el[n] = a0 * al2[0] + a1 * al2[1] + a2 * al2[2] + a3 * al2[3];
    g_er[n] = a0 * ar2[0] + a1 * ar2[1] + a2 * ar2[2] + a3 * ar2[3];
}

// ================= fused per-node GAT (H=4, D=32), warp per dst node =========
__global__ void node_gat128(const float* __restrict__ bias, int residual, int act) {
    __shared__ float4 sh[8][64];
    const int wl = threadIdx.x >> 5;
    const int lane = threadIdx.x & 31;
    const int node = (blockIdx.x * blockDim.x + threadIdx.x) >> 5;
    if (node >= NN) return;
    const int beg = g_off[node], end = g_off[node + 1];
    const float4 erd = *(const float4*)&g_er[node * 4];

    // pass A: segment max
    float m0 = -1e30f, m1 = -1e30f, m2 = -1e30f, m3 = -1e30f;
    for (int i = beg + lane; i < end; i += 32) {
        int s = g_esrc[i];
        float4 el = *(const float4*)&g_el[s * 4];
        m0 = fmaxf(m0, leaky(el.x + erd.x));
        m1 = fmaxf(m1, leaky(el.y + erd.y));
        m2 = fmaxf(m2, leaky(el.z + erd.z));
        m3 = fmaxf(m3, leaky(el.w + erd.w));
    }
#pragma unroll
    for (int o = 16; o; o >>= 1) {
        m0 = fmaxf(m0, __shfl_xor_sync(0xFFFFFFFFu, m0, o));
        m1 = fmaxf(m1, __shfl_xor_sync(0xFFFFFFFFu, m1, o));
        m2 = fmaxf(m2, __shfl_xor_sync(0xFFFFFFFFu, m2, o));
        m3 = fmaxf(m3, __shfl_xor_sync(0xFFFFFFFFu, m3, o));
    }

    // pass B: exp-sum + weighted half-feature aggregation
    float s0 = 0, s1 = 0, s2 = 0, s3 = 0;
    float a0 = 0, a1 = 0, a2 = 0, a3 = 0;
    for (int c = beg; c < end; c += 64) {
        int cnt = min(64, end - c);
        for (int t = lane; t < cnt; t += 32) {
            int s = g_esrc[c + t];
            float4 el = *(const float4*)&g_el[s * 4];
            float e0 = __expf(leaky(el.x + erd.x) - m0);
            float e1 = __expf(leaky(el.y + erd.y) - m1);
            float e2 = __expf(leaky(el.z + erd.z) - m2);
            float e3 = __expf(leaky(el.w + erd.w) - m3);
            sh[wl][t] = make_float4(e0, e1, e2, e3);
            s0 += e0; s1 += e1; s2 += e2; s3 += e3;
        }
        __syncwarp();
#pragma unroll 2
        for (int i = 0; i < cnt; i++) {
            int s = g_esrc[c + i];  // broadcast
            float4 ev = sh[wl][i];
            const __half2* fh = (const __half2*)(g_feath + (size_t)s * 128);
            float2 f01 = __half22float2(fh[lane]);
            float2 f23 = __half22float2(fh[32 + lane]);
            a0 += ev.x * f01.x;
            a1 += ev.y * f01.y;
            a2 += ev.z * f23.x;
            a3 += ev.w * f23.y;
        }
        __syncwarp();
    }
#pragma unroll
    for (int o = 16; o; o >>= 1) {
        s0 += __shfl_xor_sync(0xFFFFFFFFu, s0, o);
        s1 += __shfl_xor_sync(0xFFFFFFFFu, s1, o);
        s2 += __shfl_xor_sync(0xFFFFFFFFu, s2, o);
        s3 += __shfl_xor_sync(0xFFFFFFFFu, s3, o);
    }
    float i0 = (end > beg) ? 1.0f / s0 : 0.0f;
    float i1 = (end > beg) ? 1.0f / s1 : 0.0f;
    float i2 = (end > beg) ? 1.0f / s2 : 0.0f;
    float i3 = (end > beg) ? 1.0f / s3 : 0.0f;

    float v0 = a0 * i0 + bias[lane];
    float v1 = a1 * i1 + bias[32 + lane];
    float v2 = a2 * i2 + bias[64 + lane];
    float v3 = a3 * i3 + bias[96 + lane];
    int base = node * 128;
    if (residual) {
        v0 += g_h[base + lane];
        v1 += g_h[base + 32 + lane];
        v2 += g_h[base + 64 + lane];
        v3 += g_h[base + 96 + lane];
    }
    if (act) {
        v0 = v0 > 0.f ? v0 : __expf(v0) - 1.f;
        v1 = v1 > 0.f ? v1 : __expf(v1) - 1.f;
        v2 = v2 > 0.f ? v2 : __expf(v2) - 1.f;
        v3 = v3 > 0.f ? v3 : __expf(v3) - 1.f;
    }
    g_h[base + lane] = v0;
    g_h[base + 32 + lane] = v1;
    g_h[base + 64 + lane] = v2;
    g_h[base + 96 + lane] = v3;
}

// ================= fused per-node GAT (H=1, D=4): layer 2 ====================
__global__ void node_gat4(const float* __restrict__ bias, float* __restrict__ out) {
    const int lane = threadIdx.x & 31;
    const int node = (blockIdx.x * blockDim.x + threadIdx.x) >> 5;
    if (node >= NN) return;
    const int beg = g_off[node], end = g_off[node + 1];
    const float erd = g_er[node];

    float m = -1e30f;
    for (int i = beg + lane; i < end; i += 32) {
        int s = g_esrc[i];
        m = fmaxf(m, leaky(g_el[s] + erd));
    }
#pragma unroll
    for (int o = 16; o; o >>= 1) m = fmaxf(m, __shfl_xor_sync(0xFFFFFFFFu, m, o));

    float ssum = 0.f, ax = 0.f, ay = 0.f, az = 0.f, aw = 0.f;
    for (int i = beg + lane; i < end; i += 32) {
        int s = g_esrc[i];
        float e = __expf(leaky(g_el[s] + erd) - m);
        ssum += e;
        float4 f = *(const float4*)&g_feat4[s * 4];
        ax += e * f.x; ay += e * f.y; az += e * f.z; aw += e * f.w;
    }
#pragma unroll
    for (int o = 16; o; o >>= 1) {
        ssum += __shfl_xor_sync(0xFFFFFFFFu, ssum, o);
        ax += __shfl_xor_sync(0xFFFFFFFFu, ax, o);
        ay += __shfl_xor_sync(0xFFFFFFFFu, ay, o);
        az += __shfl_xor_sync(0xFFFFFFFFu, az, o);
        aw += __shfl_xor_sync(0xFFFFFFFFu, aw, o);
    }
    if (lane == 0) {
        float inv = (end > beg) ? 1.0f / ssum : 0.0f;
        float4 o4 = make_float4(ax * inv + bias[0], ay * inv + bias[1],
                                az * inv + bias[2], aw * inv + bias[3]);
        *(float4*)&out[node * 4] = o4;
    }
}

// ---------------- launch ----------------
extern "C" void kernel_launch(void* const* d_in, const int* in_sizes, int n_in,
                              void* d_out, int out_size) {
    const float* x   = (const float*)d_in[0];
    const int*   src = (const int*)d_in[1];
    const int*   dst = (const int*)d_in[2];
    const float* W0  = (const float*)d_in[3];
    const float* al0 = (const float*)d_in[4];
    const float* ar0 = (const float*)d_in[5];
    const float* b0  = (const float*)d_in[6];
    const float* W1  = (const float*)d_in[7];
    const float* al1 = (const float*)d_in[8];
    const float* ar1 = (const float*)d_in[9];
    const float* b1  = (const float*)d_in[10];
    const float* W2  = (const float*)d_in[11];
    const float* al2 = (const float*)d_in[12];
    const float* ar2 = (const float*)d_in[13];
    const float* b2  = (const float*)d_in[14];
    float* out = (float*)d_out;

    const int TB = 256;
    const int gN    = (NN + TB - 1) / TB;
    const int gE    = (EE + TB - 1) / TB;
    const int gNw   = (NN * 32 + TB - 1) / TB;
    const int gGemm = (NN + 63) / 64;

    // CSR by destination (shared across layers)
    k_zero<<<gN, TB>>>();
    k_hist<<<gE, TB>>>(dst);
    k_scan<<<1, 1024>>>();
    k_scatter<<<gE, TB>>>(src, dst);

    // layer 0: 64 -> 4x32, act, no residual
    gemm_fused<64, false><<<gGemm, 256>>>(x, W0, al0, ar0);
    node_gat128<<<gNw, TB>>>(b0, 0, 1);

    // layer 1: 128 -> 4x32, act, identity residual
    gemm_fused<128, true><<<gGemm, 256>>>(nullptr, W1, al1, ar1);
    node_gat128<<<gNw, TB>>>(b1, 1, 1);

    // layer 2: 128 -> 1x4, no act, no residual
    gemm_small<<<gN, TB>>>(W2, al2, ar2);
    node_gat4<<<gNw, TB>>>(b2, out);
}